// round 1
// baseline (speedup 1.0000x reference)
#include <cuda_runtime.h>
#include <mma.h>
#include <cstdint>

using namespace nvcuda;

// Problem constants (fixed shapes)
constexpr int INC  = 768;   // input channels
constexpr int CAv  = 384;   // adapter channels
constexpr int BTv  = 128;   // B*T
constexpr int Tv   = 16;
constexpr int Bv   = 8;
constexpr int Hv   = 14;
constexpr int Wv   = 14;
constexpr int Lv   = 197;
constexpr int NP   = 196;   // L-1 = H*W
constexpr int MTOT = BTv * NP;  // 25088 token rows

// Scratch buffers (device globals — no runtime allocation allowed)
__device__ float g_h0[MTOT * CAv];  // after fc1
__device__ float g_h1[MTOT * CAv];  // after conv-sum + identity
__device__ float g_h2[MTOT * CAv];  // after proj conv + residual

// GEMM tiling
#define BM 128
#define BN 64
#define BK 32

// ---------------------------------------------------------------------------
// fc1: h0[m, n] = sum_k x[token m, k] * fc1_w[n, k] + fc1_b[n]
//   A = x[:, 1:, :] rows (M=25088, K=768), B = fc1_w (N=384, K=768)
// ---------------------------------------------------------------------------
__global__ __launch_bounds__(256) void fc1_kernel(
    const float* __restrict__ x,
    const float* __restrict__ w,
    const float* __restrict__ bias)
{
    __shared__ float smem[BM * BN];           // 32 KB; reused for C tile
    float* As = smem;                          // BM*BK = 4096 floats
    float* Bs = smem + BM * BK;                // BN*BK = 2048 floats

    const int m0  = blockIdx.y * BM;
    const int n0  = blockIdx.x * BN;
    const int tid = threadIdx.x;
    const int wid = tid >> 5;
    const int wm  = wid & 3;                   // 4 warps along M
    const int wn  = wid >> 2;                  // 2 warps along N

    wmma::fragment<wmma::accumulator, 16, 16, 8, float> acc[2][2];
    #pragma unroll
    for (int i = 0; i < 2; i++)
        #pragma unroll
        for (int j = 0; j < 2; j++)
            wmma::fill_fragment(acc[i][j], 0.0f);

    // Loader mapping: each thread loads float4s; rows lr, lr+32, lr+64, lr+96
    const int lr = tid >> 3;            // 0..31
    const int lc = (tid & 7) * 4;       // 0,4,...,28

    // Precompute global row bases for the 4 A rows this thread loads
    size_t abase[4];
    #pragma unroll
    for (int i = 0; i < 4; i++) {
        int m  = m0 + lr + i * 32;
        int bt = m / NP;
        int pos = m - bt * NP;
        abase[i] = ((size_t)(bt * Lv + 1 + pos)) * INC;
    }

    for (int k0 = 0; k0 < INC; k0 += BK) {
        #pragma unroll
        for (int i = 0; i < 4; i++) {
            float4 v = *reinterpret_cast<const float4*>(&x[abase[i] + k0 + lc]);
            *reinterpret_cast<float4*>(&As[(lr + i * 32) * BK + lc]) = v;
        }
        #pragma unroll
        for (int i = 0; i < 2; i++) {
            float4 v = *reinterpret_cast<const float4*>(&w[(size_t)(n0 + lr + i * 32) * INC + k0 + lc]);
            *reinterpret_cast<float4*>(&Bs[(lr + i * 32) * BK + lc]) = v;
        }
        __syncthreads();

        #pragma unroll
        for (int kk = 0; kk < BK; kk += 8) {
            wmma::fragment<wmma::matrix_a, 16, 16, 8, wmma::precision::tf32, wmma::row_major> af[2];
            wmma::fragment<wmma::matrix_b, 16, 16, 8, wmma::precision::tf32, wmma::col_major> bf[2];
            #pragma unroll
            for (int i = 0; i < 2; i++) {
                wmma::load_matrix_sync(af[i], &As[(wm * 32 + i * 16) * BK + kk], BK);
                #pragma unroll
                for (int e = 0; e < af[i].num_elements; e++)
                    af[i].x[e] = wmma::__float_to_tf32(af[i].x[e]);
            }
            #pragma unroll
            for (int j = 0; j < 2; j++) {
                wmma::load_matrix_sync(bf[j], &Bs[(wn * 32 + j * 16) * BK + kk], BK);
                #pragma unroll
                for (int e = 0; e < bf[j].num_elements; e++)
                    bf[j].x[e] = wmma::__float_to_tf32(bf[j].x[e]);
            }
            #pragma unroll
            for (int i = 0; i < 2; i++)
                #pragma unroll
                for (int j = 0; j < 2; j++)
                    wmma::mma_sync(acc[i][j], af[i], bf[j], acc[i][j]);
        }
        __syncthreads();
    }

    // Epilogue: stage C in shared, add bias, write h0
    #pragma unroll
    for (int i = 0; i < 2; i++)
        #pragma unroll
        for (int j = 0; j < 2; j++)
            wmma::store_matrix_sync(&smem[(wm * 32 + i * 16) * BN + wn * 32 + j * 16],
                                    acc[i][j], BN, wmma::mem_row_major);
    __syncthreads();

    for (int e = tid; e < BM * BN; e += 256) {
        int r = e >> 6, c = e & 63;
        g_h0[(size_t)(m0 + r) * CAv + n0 + c] = smem[e] + bias[n0 + c];
    }
}

// ---------------------------------------------------------------------------
// conv-sum: h1 = (dw3x1x1 + dw1x3x3 + dw3x3x3)/3 + h0   (depthwise, zero pad)
// layout of h*: index = ((b*T + t)*196 + y*14 + x) * 384 + ca
// ---------------------------------------------------------------------------
__global__ __launch_bounds__(256) void conv_sum_kernel(
    const float* __restrict__ w1, const float* __restrict__ b1,
    const float* __restrict__ w2, const float* __restrict__ b2,
    const float* __restrict__ w3, const float* __restrict__ b3)
{
    int idx = blockIdx.x * 256 + threadIdx.x;
    if (idx >= MTOT * CAv) return;

    int ca  = idx % CAv;
    int sp  = idx / CAv;
    int pos = sp % NP;
    int xw  = pos % Wv;
    int yh  = pos / Wv;
    int btt = sp / NP;
    int t   = btt % Tv;
    int b   = btt / Tv;

    float acc = b1[ca] + b2[ca] + b3[ca];

    // conv1: 3x1x1 (temporal)
    #pragma unroll
    for (int kt = -1; kt <= 1; kt++) {
        int tt = t + kt;
        if (tt < 0 || tt >= Tv) continue;
        acc += w1[ca * 3 + kt + 1] *
               g_h0[((size_t)((b * Tv + tt) * NP + pos)) * CAv + ca];
    }
    // conv2: 1x3x3 (spatial)
    #pragma unroll
    for (int kh = -1; kh <= 1; kh++) {
        int yy = yh + kh;
        if (yy < 0 || yy >= Hv) continue;
        #pragma unroll
        for (int kw = -1; kw <= 1; kw++) {
            int xx = xw + kw;
            if (xx < 0 || xx >= Wv) continue;
            acc += w2[ca * 9 + (kh + 1) * 3 + kw + 1] *
                   g_h0[((size_t)((b * Tv + t) * NP + yy * Wv + xx)) * CAv + ca];
        }
    }
    // conv3: 3x3x3
    #pragma unroll
    for (int kt = -1; kt <= 1; kt++) {
        int tt = t + kt;
        if (tt < 0 || tt >= Tv) continue;
        #pragma unroll
        for (int kh = -1; kh <= 1; kh++) {
            int yy = yh + kh;
            if (yy < 0 || yy >= Hv) continue;
            #pragma unroll
            for (int kw = -1; kw <= 1; kw++) {
                int xx = xw + kw;
                if (xx < 0 || xx >= Wv) continue;
                acc += w3[ca * 27 + (kt + 1) * 9 + (kh + 1) * 3 + kw + 1] *
                       g_h0[((size_t)((b * Tv + tt) * NP + yy * Wv + xx)) * CAv + ca];
            }
        }
    }

    g_h1[idx] = acc * (1.0f / 3.0f) + g_h0[idx];
}

// ---------------------------------------------------------------------------
// proj: h2 = h1 + dwconv3x1x1(h1, proj_w) + proj_b
// ---------------------------------------------------------------------------
__global__ __launch_bounds__(256) void proj_kernel(
    const float* __restrict__ wp, const float* __restrict__ bp)
{
    int idx = blockIdx.x * 256 + threadIdx.x;
    if (idx >= MTOT * CAv) return;

    int ca  = idx % CAv;
    int sp  = idx / CAv;
    int pos = sp % NP;
    int btt = sp / NP;
    int t   = btt % Tv;
    int b   = btt / Tv;

    float acc = bp[ca];
    #pragma unroll
    for (int kt = -1; kt <= 1; kt++) {
        int tt = t + kt;
        if (tt < 0 || tt >= Tv) continue;
        acc += wp[ca * 3 + kt + 1] *
               g_h1[((size_t)((b * Tv + tt) * NP + pos)) * CAv + ca];
    }
    g_h2[idx] = g_h1[idx] + acc;
}

// ---------------------------------------------------------------------------
// fc2: out[token m, n] = x[token m, n] + sum_a h2[m, a] * fc2_w[n, a] + fc2_b[n]
//   A = h2 (M=25088, K=384), B = fc2_w (N=768, K=384)
// ---------------------------------------------------------------------------
__global__ __launch_bounds__(256) void fc2_kernel(
    const float* __restrict__ w,
    const float* __restrict__ bias,
    const float* __restrict__ x,
    float* __restrict__ out)
{
    __shared__ float smem[BM * BN];
    float* As = smem;
    float* Bs = smem + BM * BK;

    const int m0  = blockIdx.y * BM;
    const int n0  = blockIdx.x * BN;
    const int tid = threadIdx.x;
    const int wid = tid >> 5;
    const int wm  = wid & 3;
    const int wn  = wid >> 2;

    wmma::fragment<wmma::accumulator, 16, 16, 8, float> acc[2][2];
    #pragma unroll
    for (int i = 0; i < 2; i++)
        #pragma unroll
        for (int j = 0; j < 2; j++)
            wmma::fill_fragment(acc[i][j], 0.0f);

    const int lr = tid >> 3;
    const int lc = (tid & 7) * 4;

    for (int k0 = 0; k0 < CAv; k0 += BK) {
        #pragma unroll
        for (int i = 0; i < 4; i++) {
            float4 v = *reinterpret_cast<const float4*>(
                &g_h2[(size_t)(m0 + lr + i * 32) * CAv + k0 + lc]);
            *reinterpret_cast<float4*>(&As[(lr + i * 32) * BK + lc]) = v;
        }
        #pragma unroll
        for (int i = 0; i < 2; i++) {
            float4 v = *reinterpret_cast<const float4*>(
                &w[(size_t)(n0 + lr + i * 32) * CAv + k0 + lc]);
            *reinterpret_cast<float4*>(&Bs[(lr + i * 32) * BK + lc]) = v;
        }
        __syncthreads();

        #pragma unroll
        for (int kk = 0; kk < BK; kk += 8) {
            wmma::fragment<wmma::matrix_a, 16, 16, 8, wmma::precision::tf32, wmma::row_major> af[2];
            wmma::fragment<wmma::matrix_b, 16, 16, 8, wmma::precision::tf32, wmma::col_major> bf[2];
            #pragma unroll
            for (int i = 0; i < 2; i++) {
                wmma::load_matrix_sync(af[i], &As[(wm * 32 + i * 16) * BK + kk], BK);
                #pragma unroll
                for (int e = 0; e < af[i].num_elements; e++)
                    af[i].x[e] = wmma::__float_to_tf32(af[i].x[e]);
            }
            #pragma unroll
            for (int j = 0; j < 2; j++) {
                wmma::load_matrix_sync(bf[j], &Bs[(wn * 32 + j * 16) * BK + kk], BK);
                #pragma unroll
                for (int e = 0; e < bf[j].num_elements; e++)
                    bf[j].x[e] = wmma::__float_to_tf32(bf[j].x[e]);
            }
            #pragma unroll
            for (int i = 0; i < 2; i++)
                #pragma unroll
                for (int j = 0; j < 2; j++)
                    wmma::mma_sync(acc[i][j], af[i], bf[j], acc[i][j]);
        }
        __syncthreads();
    }

    #pragma unroll
    for (int i = 0; i < 2; i++)
        #pragma unroll
        for (int j = 0; j < 2; j++)
            wmma::store_matrix_sync(&smem[(wm * 32 + i * 16) * BN + wn * 32 + j * 16],
                                    acc[i][j], BN, wmma::mem_row_major);
    __syncthreads();

    for (int e = tid; e < BM * BN; e += 256) {
        int r = e >> 6, c = e & 63;
        int m = m0 + r;
        int bt = m / NP;
        int pos = m - bt * NP;
        size_t off = ((size_t)(bt * Lv + 1 + pos)) * INC + n0 + c;
        out[off] = x[off] + smem[e] + bias[n0 + c];
    }
}

// ---------------------------------------------------------------------------
// CLS row passthrough: out[:, 0, :] = x[:, 0, :]
// ---------------------------------------------------------------------------
__global__ __launch_bounds__(256) void cls_kernel(
    const float* __restrict__ x, float* __restrict__ out)
{
    int i = blockIdx.x * 256 + threadIdx.x;
    if (i >= BTv * INC) return;
    int bt = i / INC, c = i % INC;
    size_t off = (size_t)bt * Lv * INC + c;
    out[off] = x[off];
}

// ---------------------------------------------------------------------------
extern "C" void kernel_launch(void* const* d_in, const int* in_sizes, int n_in,
                              void* d_out, int out_size)
{
    const float* x     = (const float*)d_in[0];
    const float* fc1_w = (const float*)d_in[1];
    const float* fc1_b = (const float*)d_in[2];
    const float* c1w   = (const float*)d_in[3];
    const float* c1b   = (const float*)d_in[4];
    const float* c2w   = (const float*)d_in[5];
    const float* c2b   = (const float*)d_in[6];
    const float* c3w   = (const float*)d_in[7];
    const float* c3b   = (const float*)d_in[8];
    const float* pw    = (const float*)d_in[9];
    const float* pb    = (const float*)d_in[10];
    const float* fc2_w = (const float*)d_in[11];
    const float* fc2_b = (const float*)d_in[12];
    float* out = (float*)d_out;

    dim3 g1(CAv / BN, MTOT / BM);   // (6, 196)
    fc1_kernel<<<g1, 256>>>(x, fc1_w, fc1_b);

    int nel = MTOT * CAv;
    conv_sum_kernel<<<(nel + 255) / 256, 256>>>(c1w, c1b, c2w, c2b, c3w, c3b);
    proj_kernel<<<(nel + 255) / 256, 256>>>(pw, pb);

    dim3 g2(INC / BN, MTOT / BM);   // (12, 196)
    fc2_kernel<<<g2, 256>>>(fc2_w, fc2_b, x, out);

    cls_kernel<<<(BTv * INC + 255) / 256, 256>>>(x, out);
}

// round 5
// speedup vs baseline: 2.2395x; 2.2395x over previous
#include <cuda_runtime.h>
#include <mma.h>
#include <cstdint>

using namespace nvcuda;

constexpr int INC  = 768;
constexpr int CAv  = 384;
constexpr int BTv  = 128;
constexpr int Tv   = 16;
constexpr int Hv   = 14;
constexpr int Wv   = 14;
constexpr int Lv   = 197;
constexpr int NP   = 196;            // H*W
constexpr int MTOT = BTv * NP;       // 25088
constexpr int TILE3D = Tv * NP;      // 3136 elements per (b, ca)

// Scratch (device globals — no runtime allocation allowed)
// Channel-outer layout: g[ca * MTOT + m], m = bt*196 + pos
__device__ float g_h0[CAv * MTOT];
__device__ float g_h2[CAv * MTOT];

// GEMM tiling
#define BM 128
#define BN 128
#define BK 16
#define PAD_AB 20     // k-tile row stride (floats), multiple of 4
#define PAD_AT 132    // transposed A tile row stride, multiple of 4
#define PAD_CM 132    // fc1 C staging: col-major ldm (multiple of 4)
#define PAD_CR 68     // fc2 C staging: row-major ldm (multiple of 4)

constexpr int FC1_SMEM = (2 * BM * PAD_AB) > (64 * PAD_CM) ? (2 * BM * PAD_AB) : (64 * PAD_CM);   // 8448
constexpr int FC2_SMEM = (BK * PAD_AT + BM * PAD_AB) > (BM * PAD_CR) ? (BK * PAD_AT + BM * PAD_AB) : (BM * PAD_CR); // 8704

// ---------------------------------------------------------------------------
// fc1: h0[n(ca), m] = sum_k x[m, k] * w[n, k] + bias[n]   (output TRANSPOSED)
// ---------------------------------------------------------------------------
__global__ __launch_bounds__(256, 2) void fc1_kernel(
    const float* __restrict__ x,
    const float* __restrict__ w,
    const float* __restrict__ bias)
{
    __shared__ __align__(16) float smem[FC1_SMEM];
    float* As = smem;                       // [128][20]
    float* Bs = smem + BM * PAD_AB;         // [128][20]

    const int m0  = blockIdx.y * BM;
    const int n0  = blockIdx.x * BN;
    const int tid = threadIdx.x;
    const int wid = tid >> 5;
    const int wm  = wid & 1;                // 2 warps along M (64 each)
    const int wn  = wid >> 1;               // 4 warps along N (32 each)

    wmma::fragment<wmma::accumulator, 16, 16, 8, float> acc[4][2];
    #pragma unroll
    for (int i = 0; i < 4; i++)
        #pragma unroll
        for (int j = 0; j < 2; j++)
            wmma::fill_fragment(acc[i][j], 0.0f);

    // A-row global bases (2 rows per thread): rows r = idx>>2, idx = tid, tid+256
    size_t abase[2];
    #pragma unroll
    for (int u = 0; u < 2; u++) {
        int r  = (tid + u * 256) >> 2;
        int m  = m0 + r;
        int bt = m / NP;
        int pos = m - bt * NP;
        abase[u] = ((size_t)(bt * Lv + 1 + pos)) * INC;
    }

    for (int k0 = 0; k0 < INC; k0 += BK) {
        #pragma unroll
        for (int u = 0; u < 2; u++) {
            int idx = tid + u * 256;
            int r   = idx >> 2;
            int c4  = (idx & 3) * 4;
            float4 v = *reinterpret_cast<const float4*>(&x[abase[u] + k0 + c4]);
            v.x = wmma::__float_to_tf32(v.x); v.y = wmma::__float_to_tf32(v.y);
            v.z = wmma::__float_to_tf32(v.z); v.w = wmma::__float_to_tf32(v.w);
            *reinterpret_cast<float4*>(&As[r * PAD_AB + c4]) = v;
        }
        #pragma unroll
        for (int u = 0; u < 2; u++) {
            int idx = tid + u * 256;
            int r   = idx >> 2;
            int c4  = (idx & 3) * 4;
            float4 v = *reinterpret_cast<const float4*>(&w[(size_t)(n0 + r) * INC + k0 + c4]);
            v.x = wmma::__float_to_tf32(v.x); v.y = wmma::__float_to_tf32(v.y);
            v.z = wmma::__float_to_tf32(v.z); v.w = wmma::__float_to_tf32(v.w);
            *reinterpret_cast<float4*>(&Bs[r * PAD_AB + c4]) = v;
        }
        __syncthreads();

        #pragma unroll
        for (int kk = 0; kk < BK; kk += 8) {
            wmma::fragment<wmma::matrix_a, 16, 16, 8, wmma::precision::tf32, wmma::row_major> af[4];
            wmma::fragment<wmma::matrix_b, 16, 16, 8, wmma::precision::tf32, wmma::col_major> bf[2];
            #pragma unroll
            for (int i = 0; i < 4; i++)
                wmma::load_matrix_sync(af[i], &As[(wm * 64 + i * 16) * PAD_AB + kk], PAD_AB);
            #pragma unroll
            for (int j = 0; j < 2; j++)
                wmma::load_matrix_sync(bf[j], &Bs[(wn * 32 + j * 16) * PAD_AB + kk], PAD_AB);
            #pragma unroll
            for (int i = 0; i < 4; i++)
                #pragma unroll
                for (int j = 0; j < 2; j++)
                    wmma::mma_sync(acc[i][j], af[i], bf[j], acc[i][j]);
        }
        __syncthreads();
    }

    // Epilogue: two 64-col passes staged COL-MAJOR (ldm=132, mult of 4).
    // smem[col * PAD_CM + row] = C[row][col]; reads are then contiguous in row.
    #pragma unroll
    for (int pass = 0; pass < 2; pass++) {
        if ((wn >> 1) == pass) {
            #pragma unroll
            for (int i = 0; i < 4; i++)
                #pragma unroll
                for (int j = 0; j < 2; j++)
                    wmma::store_matrix_sync(
                        &smem[((wn & 1) * 32 + j * 16) * PAD_CM + wm * 64 + i * 16],
                        acc[i][j], PAD_CM, wmma::mem_col_major);
        }
        __syncthreads();
        for (int e = tid; e < BM * 64; e += 256) {
            int col = e >> 7, r = e & 127;   // warp: consecutive r -> contiguous smem
            int n = n0 + pass * 64 + col;
            g_h0[(size_t)n * MTOT + m0 + r] = smem[col * PAD_CM + r] + bias[n];
        }
        __syncthreads();
    }
}

// ---------------------------------------------------------------------------
// Fused convs: one block per (b, ca). Loads 16x196 tile once, applies the
// combined 27-tap stencil (conv1+conv2+conv3)/3 + identity, then the temporal
// proj conv + residual, writing h2 (channel-outer).
// ---------------------------------------------------------------------------
__global__ __launch_bounds__(256) void conv_fused_kernel(
    const float* __restrict__ w1, const float* __restrict__ b1,
    const float* __restrict__ w2, const float* __restrict__ b2,
    const float* __restrict__ w3, const float* __restrict__ b3,
    const float* __restrict__ wp, const float* __restrict__ pb)
{
    __shared__ float s0[TILE3D];
    __shared__ float s1[TILE3D];

    const int tid = threadIdx.x;
    const int ca  = blockIdx.x % CAv;
    const int b   = blockIdx.x / CAv;
    const size_t base = (size_t)ca * MTOT + (size_t)b * TILE3D;

    for (int i = tid; i < TILE3D; i += 256)
        s0[i] = g_h0[base + i];

    // Combined 27-tap stencil (conv2 and conv1 supports are subsets of conv3's)
    float wc[27];
    #pragma unroll
    for (int j = 0; j < 27; j++) wc[j] = w3[ca * 27 + j];
    #pragma unroll
    for (int j = 0; j < 9; j++)  wc[9 + j] += w2[ca * 9 + j];   // dt=0 plane
    #pragma unroll
    for (int dt = 0; dt < 3; dt++) wc[dt * 9 + 4] += w1[ca * 3 + dt];
    const float bias3 = (b1[ca] + b2[ca] + b3[ca]) * (1.0f / 3.0f);
    const float wp0 = wp[ca * 3], wp1 = wp[ca * 3 + 1], wp2 = wp[ca * 3 + 2];
    const float pbias = pb[ca];

    __syncthreads();

    for (int e = tid; e < TILE3D; e += 256) {
        int t   = e / NP;
        int pos = e - t * NP;
        int y   = pos / Wv;
        int x   = pos - y * Wv;
        float acc = 0.0f;
        #pragma unroll
        for (int dt = -1; dt <= 1; dt++) {
            int tt = t + dt;
            if ((unsigned)tt >= (unsigned)Tv) continue;
            #pragma unroll
            for (int dy = -1; dy <= 1; dy++) {
                int yy = y + dy;
                if ((unsigned)yy >= (unsigned)Hv) continue;
                #pragma unroll
                for (int dx = -1; dx <= 1; dx++) {
                    int xx = x + dx;
                    if ((unsigned)xx >= (unsigned)Wv) continue;
                    acc += wc[(dt + 1) * 9 + (dy + 1) * 3 + (dx + 1)]
                           * s0[tt * NP + yy * Wv + xx];
                }
            }
        }
        s1[e] = acc * (1.0f / 3.0f) + bias3 + s0[e];
    }
    __syncthreads();

    for (int e = tid; e < TILE3D; e += 256) {
        int t   = e / NP;
        float acc = pbias;
        if (t > 0)      acc += wp0 * s1[e - NP];
        acc += wp1 * s1[e];
        if (t < Tv - 1) acc += wp2 * s1[e + NP];
        g_h2[base + e] = s1[e] + acc;
    }
}

// ---------------------------------------------------------------------------
// fc2: out[m, n] = x[m, n] + sum_k h2[k, m] * w[n, k] + bias[n]
//   A is the TRANSPOSED h2 (col-major fragment), K = 384
// ---------------------------------------------------------------------------
__global__ __launch_bounds__(256, 2) void fc2_kernel(
    const float* __restrict__ w,
    const float* __restrict__ bias,
    const float* __restrict__ x,
    float* __restrict__ out)
{
    __shared__ __align__(16) float smem[FC2_SMEM];
    float* As = smem;                        // [16][132]  (k rows, m cols)
    float* Bs = smem + BK * PAD_AT;          // [128][20]

    const int m0  = blockIdx.y * BM;
    const int n0  = blockIdx.x * BN;
    const int tid = threadIdx.x;
    const int wid = tid >> 5;
    const int wm  = wid & 1;
    const int wn  = wid >> 1;

    wmma::fragment<wmma::accumulator, 16, 16, 8, float> acc[4][2];
    #pragma unroll
    for (int i = 0; i < 4; i++)
        #pragma unroll
        for (int j = 0; j < 2; j++)
            wmma::fill_fragment(acc[i][j], 0.0f);

    for (int k0 = 0; k0 < CAv; k0 += BK) {
        // A: 16 k-rows x 128 m, contiguous along m in g_h2
        #pragma unroll
        for (int u = 0; u < 2; u++) {
            int idx = tid + u * 256;
            int kr  = idx >> 5;
            int mc4 = (idx & 31) * 4;
            float4 v = *reinterpret_cast<const float4*>(
                &g_h2[(size_t)(k0 + kr) * MTOT + m0 + mc4]);
            v.x = wmma::__float_to_tf32(v.x); v.y = wmma::__float_to_tf32(v.y);
            v.z = wmma::__float_to_tf32(v.z); v.w = wmma::__float_to_tf32(v.w);
            *reinterpret_cast<float4*>(&As[kr * PAD_AT + mc4]) = v;
        }
        #pragma unroll
        for (int u = 0; u < 2; u++) {
            int idx = tid + u * 256;
            int r   = idx >> 2;
            int c4  = (idx & 3) * 4;
            float4 v = *reinterpret_cast<const float4*>(&w[(size_t)(n0 + r) * CAv + k0 + c4]);
            v.x = wmma::__float_to_tf32(v.x); v.y = wmma::__float_to_tf32(v.y);
            v.z = wmma::__float_to_tf32(v.z); v.w = wmma::__float_to_tf32(v.w);
            *reinterpret_cast<float4*>(&Bs[r * PAD_AB + c4]) = v;
        }
        __syncthreads();

        #pragma unroll
        for (int kk = 0; kk < BK; kk += 8) {
            wmma::fragment<wmma::matrix_a, 16, 16, 8, wmma::precision::tf32, wmma::col_major> af[4];
            wmma::fragment<wmma::matrix_b, 16, 16, 8, wmma::precision::tf32, wmma::col_major> bf[2];
            #pragma unroll
            for (int i = 0; i < 4; i++)
                wmma::load_matrix_sync(af[i], &As[kk * PAD_AT + wm * 64 + i * 16], PAD_AT);
            #pragma unroll
            for (int j = 0; j < 2; j++)
                wmma::load_matrix_sync(bf[j], &Bs[(wn * 32 + j * 16) * PAD_AB + kk], PAD_AB);
            #pragma unroll
            for (int i = 0; i < 4; i++)
                #pragma unroll
                for (int j = 0; j < 2; j++)
                    wmma::mma_sync(acc[i][j], af[i], bf[j], acc[i][j]);
        }
        __syncthreads();
    }

    // Epilogue: two passes, ROW-MAJOR staging (ldm=68, mult of 4); out row-major
    #pragma unroll
    for (int pass = 0; pass < 2; pass++) {
        if ((wn >> 1) == pass) {
            #pragma unroll
            for (int i = 0; i < 4; i++)
                #pragma unroll
                for (int j = 0; j < 2; j++)
                    wmma::store_matrix_sync(
                        &smem[(wm * 64 + i * 16) * PAD_CR + (wn & 1) * 32 + j * 16],
                        acc[i][j], PAD_CR, wmma::mem_row_major);
        }
        __syncthreads();
        for (int e = tid; e < BM * 64; e += 256) {
            int c = e & 63, r = e >> 6;      // warp: consecutive c -> contiguous smem
            int m = m0 + r;
            int bt = m / NP;
            int pos = m - bt * NP;
            int n = n0 + pass * 64 + c;
            size_t off = ((size_t)(bt * Lv + 1 + pos)) * INC + n;
            out[off] = x[off] + smem[r * PAD_CR + c] + bias[n];
        }
        __syncthreads();
    }
}

// ---------------------------------------------------------------------------
__global__ __launch_bounds__(256) void cls_kernel(
    const float* __restrict__ x, float* __restrict__ out)
{
    int i = blockIdx.x * 256 + threadIdx.x;
    if (i >= BTv * INC) return;
    int bt = i / INC, c = i % INC;
    size_t off = (size_t)bt * Lv * INC + c;
    out[off] = x[off];
}

// ---------------------------------------------------------------------------
extern "C" void kernel_launch(void* const* d_in, const int* in_sizes, int n_in,
                              void* d_out, int out_size)
{
    const float* x     = (const float*)d_in[0];
    const float* fc1_w = (const float*)d_in[1];
    const float* fc1_b = (const float*)d_in[2];
    const float* c1w   = (const float*)d_in[3];
    const float* c1b   = (const float*)d_in[4];
    const float* c2w   = (const float*)d_in[5];
    const float* c2b   = (const float*)d_in[6];
    const float* c3w   = (const float*)d_in[7];
    const float* c3b   = (const float*)d_in[8];
    const float* pw    = (const float*)d_in[9];
    const float* pb    = (const float*)d_in[10];
    const float* fc2_w = (const float*)d_in[11];
    const float* fc2_b = (const float*)d_in[12];
    float* out = (float*)d_out;

    dim3 g1(CAv / BN, MTOT / BM);   // (3, 196)
    fc1_kernel<<<g1, 256>>>(x, fc1_w, fc1_b);

    conv_fused_kernel<<<CAv * (BTv / Tv), 256>>>(c1w, c1b, c2w, c2b, c3w, c3b, pw, pb);

    dim3 g2(INC / BN, MTOT / BM);   // (6, 196)
    fc2_kernel<<<g2, 256>>>(fc2_w, fc2_b, x, out);

    cls_kernel<<<(BTv * INC + 255) / 256, 256>>>(x, out);
}

// round 6
// speedup vs baseline: 2.4085x; 1.0755x over previous
#include <cuda_runtime.h>
#include <mma.h>
#include <cstdint>

using namespace nvcuda;

constexpr int INC  = 768;
constexpr int CAv  = 384;
constexpr int BTv  = 128;
constexpr int Tv   = 16;
constexpr int Hv   = 14;
constexpr int Wv   = 14;
constexpr int Lv   = 197;
constexpr int NP   = 196;            // H*W
constexpr int MTOT = BTv * NP;       // 25088
constexpr int TILE3D = Tv * NP;      // 3136 elements per (b, ca)

// Scratch (device globals — no runtime allocation allowed)
__device__ float g_h0[CAv * MTOT];   // channel-outer: [ca][m]
__device__ float g_h2[CAv * MTOT];

// GEMM tiling
#define BM 128
#define BN 128
#define BK 16
#define PAD_AB 20     // k-tile row stride (floats); 80B row -> 16B aligned
#define PAD_AT 132    // transposed A tile row stride; 528B row -> 16B aligned
#define PAD_CM 132    // fc1 C staging: col-major ldm (multiple of 4)
#define PAD_CR 68     // fc2 C staging: row-major ldm (multiple of 4)

// Double-buffered smem sizes
constexpr int FC1_AB   = BM * PAD_AB;            // 2560 floats per buffer
constexpr int FC1_SMEM = (4 * FC1_AB) > (64 * PAD_CM) ? (4 * FC1_AB) : (64 * PAD_CM);    // 10240
constexpr int FC2_A    = BK * PAD_AT;            // 2112
constexpr int FC2_B    = BM * PAD_AB;            // 2560
constexpr int FC2_SMEM = (2 * (FC2_A + FC2_B)) > (BM * PAD_CR) ? (2 * (FC2_A + FC2_B)) : (BM * PAD_CR);  // 9344

// ---------------------------------------------------------------------------
__device__ __forceinline__ void cp_async16(float* smem_dst, const float* gmem_src) {
    uint32_t s = (uint32_t)__cvta_generic_to_shared(smem_dst);
    asm volatile("cp.async.cg.shared.global [%0], [%1], 16;\n" :: "r"(s), "l"(gmem_src));
}
__device__ __forceinline__ void cp_commit() {
    asm volatile("cp.async.commit_group;\n");
}
__device__ __forceinline__ void cp_wait1() {
    asm volatile("cp.async.wait_group 1;\n");
}

// ---------------------------------------------------------------------------
// fc1: h0[n(ca), m] = sum_k x[m, k] * w[n, k] + bias[n]   (output TRANSPOSED)
// ---------------------------------------------------------------------------
__global__ __launch_bounds__(256, 2) void fc1_kernel(
    const float* __restrict__ x,
    const float* __restrict__ w,
    const float* __restrict__ bias)
{
    __shared__ __align__(16) float smem[FC1_SMEM];
    // buffers: As[s] = smem + s*2*FC1_AB, Bs[s] = As[s] + FC1_AB

    const int m0  = blockIdx.y * BM;
    const int n0  = blockIdx.x * BN;
    const int tid = threadIdx.x;
    const int wid = tid >> 5;
    const int wm  = wid & 1;                // 2 warps along M (64 each)
    const int wn  = wid >> 1;               // 4 warps along N (32 each)

    wmma::fragment<wmma::accumulator, 16, 16, 8, float> acc[4][2];
    #pragma unroll
    for (int i = 0; i < 4; i++)
        #pragma unroll
        for (int j = 0; j < 2; j++)
            wmma::fill_fragment(acc[i][j], 0.0f);

    // Loader mapping: idx = tid + u*256; row = idx>>2 (0..127), col4 = (idx&3)*4
    size_t abase[2];
    size_t bbase[2];
    int lrow[2], lcol[2];
    #pragma unroll
    for (int u = 0; u < 2; u++) {
        int idx = tid + u * 256;
        int r   = idx >> 2;
        lrow[u] = r;
        lcol[u] = (idx & 3) * 4;
        int m  = m0 + r;
        int bt = m / NP;
        int pos = m - bt * NP;
        abase[u] = ((size_t)(bt * Lv + 1 + pos)) * INC;
        bbase[u] = (size_t)(n0 + r) * INC;
    }

    constexpr int KT = INC / BK;   // 48

    // Prefetch tile 0 into buffer 0
    {
        float* As = smem;
        float* Bs = smem + FC1_AB;
        #pragma unroll
        for (int u = 0; u < 2; u++) {
            cp_async16(&As[lrow[u] * PAD_AB + lcol[u]], &x[abase[u] + lcol[u]]);
            cp_async16(&Bs[lrow[u] * PAD_AB + lcol[u]], &w[bbase[u] + lcol[u]]);
        }
        cp_commit();
    }

    for (int kt = 0; kt < KT; kt++) {
        // Prefetch tile kt+1 into the other buffer
        if (kt + 1 < KT) {
            int k0n = (kt + 1) * BK;
            float* As = smem + ((kt + 1) & 1) * 2 * FC1_AB;
            float* Bs = As + FC1_AB;
            #pragma unroll
            for (int u = 0; u < 2; u++) {
                cp_async16(&As[lrow[u] * PAD_AB + lcol[u]], &x[abase[u] + k0n + lcol[u]]);
                cp_async16(&Bs[lrow[u] * PAD_AB + lcol[u]], &w[bbase[u] + k0n + lcol[u]]);
            }
        }
        cp_commit();
        cp_wait1();               // tile kt resident
        __syncthreads();

        float* As = smem + (kt & 1) * 2 * FC1_AB;
        float* Bs = As + FC1_AB;
        #pragma unroll
        for (int kk = 0; kk < BK; kk += 8) {
            wmma::fragment<wmma::matrix_a, 16, 16, 8, wmma::precision::tf32, wmma::row_major> af[4];
            wmma::fragment<wmma::matrix_b, 16, 16, 8, wmma::precision::tf32, wmma::col_major> bf[2];
            #pragma unroll
            for (int i = 0; i < 4; i++)
                wmma::load_matrix_sync(af[i], &As[(wm * 64 + i * 16) * PAD_AB + kk], PAD_AB);
            #pragma unroll
            for (int j = 0; j < 2; j++)
                wmma::load_matrix_sync(bf[j], &Bs[(wn * 32 + j * 16) * PAD_AB + kk], PAD_AB);
            #pragma unroll
            for (int i = 0; i < 4; i++)
                #pragma unroll
                for (int j = 0; j < 2; j++)
                    wmma::mma_sync(acc[i][j], af[i], bf[j], acc[i][j]);
        }
        __syncthreads();           // compute done before this buffer is refilled
    }

    // Epilogue: two 64-col passes staged COL-MAJOR (ldm=132, mult of 4)
    #pragma unroll
    for (int pass = 0; pass < 2; pass++) {
        if ((wn >> 1) == pass) {
            #pragma unroll
            for (int i = 0; i < 4; i++)
                #pragma unroll
                for (int j = 0; j < 2; j++)
                    wmma::store_matrix_sync(
                        &smem[((wn & 1) * 32 + j * 16) * PAD_CM + wm * 64 + i * 16],
                        acc[i][j], PAD_CM, wmma::mem_col_major);
        }
        __syncthreads();
        for (int e = tid; e < BM * 64; e += 256) {
            int col = e >> 7, r = e & 127;
            int n = n0 + pass * 64 + col;
            g_h0[(size_t)n * MTOT + m0 + r] = smem[col * PAD_CM + r] + bias[n];
        }
        __syncthreads();
    }
}

// ---------------------------------------------------------------------------
// Fused convs: one block per (b, ca). Combined 27-tap stencil + identity,
// then temporal proj conv + residual, writing h2 (channel-outer).
// ---------------------------------------------------------------------------
__global__ __launch_bounds__(256) void conv_fused_kernel(
    const float* __restrict__ w1, const float* __restrict__ b1,
    const float* __restrict__ w2, const float* __restrict__ b2,
    const float* __restrict__ w3, const float* __restrict__ b3,
    const float* __restrict__ wp, const float* __restrict__ pb)
{
    __shared__ float s0[TILE3D];
    __shared__ float s1[TILE3D];

    const int tid = threadIdx.x;
    const int ca  = blockIdx.x % CAv;
    const int b   = blockIdx.x / CAv;
    const size_t base = (size_t)ca * MTOT + (size_t)b * TILE3D;

    for (int i = tid * 4; i < TILE3D; i += 1024)
        *reinterpret_cast<float4*>(&s0[i]) =
            *reinterpret_cast<const float4*>(&g_h0[base + i]);

    float wc[27];
    #pragma unroll
    for (int j = 0; j < 27; j++) wc[j] = w3[ca * 27 + j];
    #pragma unroll
    for (int j = 0; j < 9; j++)  wc[9 + j] += w2[ca * 9 + j];   // dt=0 plane
    #pragma unroll
    for (int dt = 0; dt < 3; dt++) wc[dt * 9 + 4] += w1[ca * 3 + dt];
    const float bias3 = (b1[ca] + b2[ca] + b3[ca]) * (1.0f / 3.0f);
    const float wp0 = wp[ca * 3], wp1 = wp[ca * 3 + 1], wp2 = wp[ca * 3 + 2];
    const float pbias = pb[ca];

    __syncthreads();

    for (int e = tid; e < TILE3D; e += 256) {
        int t   = e / NP;
        int pos = e - t * NP;
        int y   = pos / Wv;
        int x   = pos - y * Wv;
        float acc = 0.0f;
        #pragma unroll
        for (int dt = -1; dt <= 1; dt++) {
            int tt = t + dt;
            if ((unsigned)tt >= (unsigned)Tv) continue;
            #pragma unroll
            for (int dy = -1; dy <= 1; dy++) {
                int yy = y + dy;
                if ((unsigned)yy >= (unsigned)Hv) continue;
                #pragma unroll
                for (int dx = -1; dx <= 1; dx++) {
                    int xx = x + dx;
                    if ((unsigned)xx >= (unsigned)Wv) continue;
                    acc += wc[(dt + 1) * 9 + (dy + 1) * 3 + (dx + 1)]
                           * s0[tt * NP + yy * Wv + xx];
                }
            }
        }
        s1[e] = acc * (1.0f / 3.0f) + bias3 + s0[e];
    }
    __syncthreads();

    for (int e = tid; e < TILE3D; e += 256) {
        int t   = e / NP;
        float acc = pbias;
        if (t > 0)      acc += wp0 * s1[e - NP];
        acc += wp1 * s1[e];
        if (t < Tv - 1) acc += wp2 * s1[e + NP];
        g_h2[base + e] = s1[e] + acc;
    }
}

// ---------------------------------------------------------------------------
// fc2: out[m, n] = x[m, n] + sum_k h2[k, m] * w[n, k] + bias[n]
// ---------------------------------------------------------------------------
__global__ __launch_bounds__(256, 2) void fc2_kernel(
    const float* __restrict__ w,
    const float* __restrict__ bias,
    const float* __restrict__ x,
    float* __restrict__ out)
{
    __shared__ __align__(16) float smem[FC2_SMEM];
    // As[s] = smem + s*(FC2_A+FC2_B); Bs[s] = As[s] + FC2_A

    const int m0  = blockIdx.y * BM;
    const int n0  = blockIdx.x * BN;
    const int tid = threadIdx.x;
    const int wid = tid >> 5;
    const int wm  = wid & 1;
    const int wn  = wid >> 1;

    wmma::fragment<wmma::accumulator, 16, 16, 8, float> acc[4][2];
    #pragma unroll
    for (int i = 0; i < 4; i++)
        #pragma unroll
        for (int j = 0; j < 2; j++)
            wmma::fill_fragment(acc[i][j], 0.0f);

    // A loader: idx -> kr = idx>>5 (0..15), mc4 = (idx&31)*4
    // B loader: idx -> r = idx>>2 (0..127), c4 = (idx&3)*4
    int akr[2], amc[2], brow[2], bcol[2];
    size_t bbase[2];
    #pragma unroll
    for (int u = 0; u < 2; u++) {
        int idx = tid + u * 256;
        akr[u] = idx >> 5;
        amc[u] = (idx & 31) * 4;
        brow[u] = idx >> 2;
        bcol[u] = (idx & 3) * 4;
        bbase[u] = (size_t)(n0 + brow[u]) * CAv;
    }

    constexpr int KT = CAv / BK;   // 24

    {
        float* As = smem;
        float* Bs = smem + FC2_A;
        #pragma unroll
        for (int u = 0; u < 2; u++) {
            cp_async16(&As[akr[u] * PAD_AT + amc[u]],
                       &g_h2[(size_t)akr[u] * MTOT + m0 + amc[u]]);
            cp_async16(&Bs[brow[u] * PAD_AB + bcol[u]], &w[bbase[u] + bcol[u]]);
        }
        cp_commit();
    }

    for (int kt = 0; kt < KT; kt++) {
        if (kt + 1 < KT) {
            int k0n = (kt + 1) * BK;
            float* As = smem + ((kt + 1) & 1) * (FC2_A + FC2_B);
            float* Bs = As + FC2_A;
            #pragma unroll
            for (int u = 0; u < 2; u++) {
                cp_async16(&As[akr[u] * PAD_AT + amc[u]],
                           &g_h2[(size_t)(k0n + akr[u]) * MTOT + m0 + amc[u]]);
                cp_async16(&Bs[brow[u] * PAD_AB + bcol[u]], &w[bbase[u] + k0n + bcol[u]]);
            }
        }
        cp_commit();
        cp_wait1();
        __syncthreads();

        float* As = smem + (kt & 1) * (FC2_A + FC2_B);
        float* Bs = As + FC2_A;
        #pragma unroll
        for (int kk = 0; kk < BK; kk += 8) {
            wmma::fragment<wmma::matrix_a, 16, 16, 8, wmma::precision::tf32, wmma::col_major> af[4];
            wmma::fragment<wmma::matrix_b, 16, 16, 8, wmma::precision::tf32, wmma::col_major> bf[2];
            #pragma unroll
            for (int i = 0; i < 4; i++)
                wmma::load_matrix_sync(af[i], &As[kk * PAD_AT + wm * 64 + i * 16], PAD_AT);
            #pragma unroll
            for (int j = 0; j < 2; j++)
                wmma::load_matrix_sync(bf[j], &Bs[(wn * 32 + j * 16) * PAD_AB + kk], PAD_AB);
            #pragma unroll
            for (int i = 0; i < 4; i++)
                #pragma unroll
                for (int j = 0; j < 2; j++)
                    wmma::mma_sync(acc[i][j], af[i], bf[j], acc[i][j]);
        }
        __syncthreads();
    }

    // Epilogue: two passes, ROW-MAJOR staging (ldm=68)
    #pragma unroll
    for (int pass = 0; pass < 2; pass++) {
        if ((wn >> 1) == pass) {
            #pragma unroll
            for (int i = 0; i < 4; i++)
                #pragma unroll
                for (int j = 0; j < 2; j++)
                    wmma::store_matrix_sync(
                        &smem[(wm * 64 + i * 16) * PAD_CR + (wn & 1) * 32 + j * 16],
                        acc[i][j], PAD_CR, wmma::mem_row_major);
        }
        __syncthreads();
        for (int e = tid; e < BM * 64; e += 256) {
            int c = e & 63, r = e >> 6;
            int m = m0 + r;
            int bt = m / NP;
            int pos = m - bt * NP;
            int n = n0 + pass * 64 + c;
            size_t off = ((size_t)(bt * Lv + 1 + pos)) * INC + n;
            out[off] = x[off] + smem[r * PAD_CR + c] + bias[n];
        }
        __syncthreads();
    }
}

// ---------------------------------------------------------------------------
__global__ __launch_bounds__(256) void cls_kernel(
    const float* __restrict__ x, float* __restrict__ out)
{
    int i = blockIdx.x * 256 + threadIdx.x;
    if (i >= BTv * INC) return;
    int bt = i / INC, c = i % INC;
    size_t off = (size_t)bt * Lv * INC + c;
    out[off] = x[off];
}

// ---------------------------------------------------------------------------
extern "C" void kernel_launch(void* const* d_in, const int* in_sizes, int n_in,
                              void* d_out, int out_size)
{
    const float* x     = (const float*)d_in[0];
    const float* fc1_w = (const float*)d_in[1];
    const float* fc1_b = (const float*)d_in[2];
    const float* c1w   = (const float*)d_in[3];
    const float* c1b   = (const float*)d_in[4];
    const float* c2w   = (const float*)d_in[5];
    const float* c2b   = (const float*)d_in[6];
    const float* c3w   = (const float*)d_in[7];
    const float* c3b   = (const float*)d_in[8];
    const float* pw    = (const float*)d_in[9];
    const float* pb    = (const float*)d_in[10];
    const float* fc2_w = (const float*)d_in[11];
    const float* fc2_b = (const float*)d_in[12];
    float* out = (float*)d_out;

    dim3 g1(CAv / BN, MTOT / BM);   // (3, 196)
    fc1_kernel<<<g1, 256>>>(x, fc1_w, fc1_b);

    conv_fused_kernel<<<CAv * (BTv / Tv), 256>>>(c1w, c1b, c2w, c2b, c3w, c3b, pw, pb);

    dim3 g2(INC / BN, MTOT / BM);   // (6, 196)
    fc2_kernel<<<g2, 256>>>(fc2_w, fc2_b, x, out);

    cls_kernel<<<(BTv * INC + 255) / 256, 256>>>(x, out);
}